// round 9
// baseline (speedup 1.0000x reference)
#include <cuda_runtime.h>
#include <cuda_fp16.h>
#include <cstdint>

#define B_ROWS 65536
#define D_IN   784
#define D_H    1024
#define N_CLS  10
#define BN_EPS 1e-5f
#define KP     1600            // 2*784 fp16 planes + 32 zero pad = 25 * 64
#define KREAL  1568
#define BK     64
#define NIT    (KP / BK)       // 25
#define BMT    128
#define BNT    128
#define SROWB  144             // smem row stride bytes (128 data + 16 pad)
#define STAGE_B ((BMT + BNT) * SROWB)  // 36864 bytes
#define NSTAGE 3
#define TILES  ((B_ROWS / BMT) * (D_H / BNT))   // 4096

// ---------------- device scratch ---------------------------------------------
__device__ __half g_xb[(size_t)B_ROWS * KP];   // x split into 2 fp16 planes
__device__ __half g_sb[(size_t)D_H * KP];      // sign(w1) tiled 2x, fp16
__device__ float    g_h[(size_t)B_ROWS * D_H];
__device__ float    g_sum[D_H];
__device__ float    g_sumsq[D_H];
__device__ unsigned g_tbits[N_CLS][32];

// ---------------- PTX helpers -------------------------------------------------
__device__ __forceinline__ uint32_t s2u(const void* p) {
    uint32_t a;
    asm("{ .reg .u64 t; cvta.to.shared.u64 t, %1; cvt.u32.u64 %0, t; }" : "=r"(a) : "l"(p));
    return a;
}
__device__ __forceinline__ void cpa16(uint32_t s, const void* g) {
    asm volatile("cp.async.cg.shared.global [%0], [%1], 16;" :: "r"(s), "l"(g) : "memory");
}
__device__ __forceinline__ void cp_commit() {
    asm volatile("cp.async.commit_group;" ::: "memory");
}
__device__ __forceinline__ void ldm4(uint32_t* a, uint32_t addr) {
    asm volatile("ldmatrix.sync.aligned.m8n8.x4.shared.b16 {%0,%1,%2,%3}, [%4];"
                 : "=r"(a[0]), "=r"(a[1]), "=r"(a[2]), "=r"(a[3]) : "r"(addr));
}
__device__ __forceinline__ void mma16816(float* c, const uint32_t* a, const uint32_t* b) {
    asm volatile("mma.sync.aligned.m16n8k16.row.col.f32.f16.f16.f32 "
                 "{%0,%1,%2,%3}, {%4,%5,%6,%7}, {%8,%9}, {%0,%1,%2,%3};"
                 : "+f"(c[0]), "+f"(c[1]), "+f"(c[2]), "+f"(c[3])
                 : "r"(a[0]), "r"(a[1]), "r"(a[2]), "r"(a[3]), "r"(b[0]), "r"(b[1]));
}

// ---------------- fused prep: convert x, binarize w1, pack w2, zero stats ----
#define CONV_B  ((B_ROWS * (D_IN / 4) + 255) / 256)    // 50176
#define PREP_B  ((D_H * KP + 255) / 256)               // 6400
#define PAD_B   ((B_ROWS * 4 + 255) / 256)             // 1024

__global__ void prep_all_kernel(const float* __restrict__ x,
                                const float* __restrict__ w1,
                                const float* __restrict__ w2) {
    int b = blockIdx.x;
    if (b < CONV_B) {
        size_t i = (size_t)b * 256 + threadIdx.x;
        if (i >= (size_t)B_ROWS * (D_IN / 4)) return;
        size_t m = i / (D_IN / 4);
        int k4 = (int)(i % (D_IN / 4)) * 4;
        float4 v = *(const float4*)(x + m * D_IN + k4);
        float f[4] = {v.x, v.y, v.z, v.w};
        __half2 hi2[2], lo2[2];
        #pragma unroll
        for (int j = 0; j < 2; j++) {
            __half h0 = __float2half_rn(f[2*j]);
            __half h1 = __float2half_rn(f[2*j+1]);
            float r0 = f[2*j]   - __half2float(h0);
            float r1 = f[2*j+1] - __half2float(h1);
            hi2[j] = __halves2half2(h0, h1);
            lo2[j] = __halves2half2(__float2half_rn(r0), __float2half_rn(r1));
        }
        __half2* row = (__half2*)(g_xb + m * KP);
        int p = k4 >> 1;
        row[p]          = hi2[0];  row[p + 1]          = hi2[1];
        row[p + D_IN/2] = lo2[0];  row[p + D_IN/2 + 1] = lo2[1];
    } else if (b < CONV_B + PREP_B) {
        int i = (b - CONV_B) * 256 + threadIdx.x;
        if (i < D_H * KP) {
            int n = i / KP, k = i % KP;
            float s = 0.f;
            if (k < KREAL) {
                float v = w1[n * D_IN + (k % D_IN)];
                s = (v > 0.f) ? 1.f : (v < 0.f ? -1.f : 0.f);
            }
            g_sb[i] = __float2half_rn(s);
        }
        if (i < D_H) { g_sum[i] = 0.f; g_sumsq[i] = 0.f; }
        if (i < N_CLS * 32) {
            int c = i >> 5, g = i & 31;
            unsigned w = 0;
            #pragma unroll
            for (int l = 0; l < 32; l++) {
                float v = w2[c * D_H + g * 32 + l];
                if (v > 0.f) w |= (1u << l);
            }
            g_tbits[c][g] = w;
        }
    } else {
        int i = (b - CONV_B - PREP_B) * 256 + threadIdx.x;
        if (i < B_ROWS * 4) {
            size_t row = (size_t)(i >> 2);
            *(uint4*)((char*)(g_xb + row * KP + KREAL) + (i & 3) * 16) =
                make_uint4(0, 0, 0, 0);
        }
    }
}

// ---------------- GEMM1 + fused BN stats (persistent, cross-tile pipeline) ---
// CTA tile 128x128, 4 warps (2x2), warp tile 64x64, BK=64, 3-stage cp.async
// ring that runs continuously across tiles. 2 CTAs/SM. bn = tile & 7 fixed
// per CTA when gridDim.x % 8 == 0 (B slab L2-resident).
__global__ __launch_bounds__(128, 2)
void gemm1_kernel() {
    extern __shared__ char smem[];
    const uint32_t sb = s2u(smem);
    const int tid = threadIdx.x, wid = tid >> 5, lane = tid & 31;
    const int warp_m = wid >> 1, warp_n = wid & 1;     // 2 x 2
    const int GRID = gridDim.x;

    auto load_chunk = [&](const __half* A_, const __half* B_, int k0, int stage) {
        uint32_t sA = sb + stage * STAGE_B;
        uint32_t sBs = sA + BMT * SROWB;
        #pragma unroll
        for (int j = 0; j < 8; j++) {
            int idx = tid + j * 128;
            int row = idx >> 3, q = idx & 7;
            cpa16(sA + row * SROWB + q * 16,
                  (const char*)(A_ + (size_t)row * KP + k0) + q * 16);
        }
        #pragma unroll
        for (int j = 0; j < 8; j++) {
            int idx = tid + j * 128;
            int row = idx >> 3, q = idx & 7;
            cpa16(sBs + row * SROWB + q * 16,
                  (const char*)(B_ + (size_t)row * KP + k0) + q * 16);
        }
        cp_commit();
    };

    // ldmatrix intra-tile offsets
    const uint32_t a_off = (warp_m * 64 + (lane & 15)) * SROWB + (lane >> 4) * 16;
    const uint32_t b_off = (warp_n * 64 + (lane & 7) + ((lane >> 4) << 3)) * SROWB
                         + ((lane >> 3) & 1) * 16;

    // load cursor (tile lt, chunk lc, stage ls)
    int lt = blockIdx.x, lc = 0, ls = 0;
    const __half* lA = g_xb + (size_t)(lt >> 3) * BMT * KP;
    const __half* lB = g_sb + (size_t)(lt & 7) * BNT * KP;
    auto adv = [&]() {
        if (++lc == NIT) {
            lc = 0; lt += GRID;
            if (lt < TILES) {
                lA = g_xb + (size_t)(lt >> 3) * BMT * KP;
                lB = g_sb + (size_t)(lt & 7) * BNT * KP;
            }
        }
    };

    float acc[4][8][4];
    #pragma unroll
    for (int i = 0; i < 4; i++)
        #pragma unroll
        for (int j = 0; j < 8; j++)
            #pragma unroll
            for (int r = 0; r < 4; r++) acc[i][j][r] = 0.f;

    if (blockIdx.x >= TILES) return;

    // prologue: fill 2 stages
    load_chunk(lA, lB, lc * BK, 0); adv();
    load_chunk(lA, lB, lc * BK, 1); adv();
    ls = 2;
    int cs = 0;

    uint32_t fa[2][4][4], fb[2][4][4];

    for (int t = blockIdx.x; t < TILES; t += GRID) {
        for (int i = 0; i < NIT; i++) {
            asm volatile("cp.async.wait_group 1;" ::: "memory");
            __syncthreads();
            uint32_t sA = sb + cs * STAGE_B;
            uint32_t sBs = sA + BMT * SROWB;

            // prefetch ks=0 fragments
            #pragma unroll
            for (int mt = 0; mt < 4; mt++)
                ldm4(fa[0][mt], sA + a_off + mt * 16 * SROWB);
            #pragma unroll
            for (int np = 0; np < 4; np++)
                ldm4(fb[0][np], sBs + b_off + np * 16 * SROWB);

            if (lt < TILES) { load_chunk(lA, lB, lc * BK, ls); adv(); }
            else cp_commit();
            ls = (ls == 2) ? 0 : ls + 1;

            #pragma unroll
            for (int ks = 0; ks < 4; ks++) {
                int cur = ks & 1;
                if (ks < 3) {
                    int nb = cur ^ 1;
                    uint32_t ko = (ks + 1) * 32;
                    #pragma unroll
                    for (int mt = 0; mt < 4; mt++)
                        ldm4(fa[nb][mt], sA + a_off + mt * 16 * SROWB + ko);
                    #pragma unroll
                    for (int np = 0; np < 4; np++)
                        ldm4(fb[nb][np], sBs + b_off + np * 16 * SROWB + ko);
                }
                #pragma unroll
                for (int mt = 0; mt < 4; mt++)
                    #pragma unroll
                    for (int nt = 0; nt < 8; nt++)
                        mma16816(acc[mt][nt], fa[cur][mt], fb[cur][nt >> 1] + (nt & 1) * 2);
            }
            cs = (cs == 2) ? 0 : cs + 1;
        }

        // ---------------- epilogue for tile t (overlaps next tile's loads) ---
        int bm = t >> 3, bn = t & 7;
        float* Hb = g_h + (size_t)(bm * BMT) * D_H + bn * BNT;
        #pragma unroll
        for (int mt = 0; mt < 4; mt++) {
            int r0 = warp_m * 64 + mt * 16 + (lane >> 2);
            #pragma unroll
            for (int nt = 0; nt < 8; nt++) {
                int c = warp_n * 64 + nt * 8 + (lane & 3) * 2;
                *(float2*)(Hb + (size_t)r0 * D_H + c)       = make_float2(acc[mt][nt][0], acc[mt][nt][1]);
                *(float2*)(Hb + (size_t)(r0 + 8) * D_H + c) = make_float2(acc[mt][nt][2], acc[mt][nt][3]);
            }
        }
        #pragma unroll
        for (int nt = 0; nt < 8; nt++) {
            float s0 = 0.f, s1 = 0.f, q0 = 0.f, q1 = 0.f;
            #pragma unroll
            for (int mt = 0; mt < 4; mt++) {
                float a0 = acc[mt][nt][0], a1 = acc[mt][nt][1];
                float a2 = acc[mt][nt][2], a3 = acc[mt][nt][3];
                s0 += a0 + a2; s1 += a1 + a3;
                q0 = fmaf(a0, a0, q0); q0 = fmaf(a2, a2, q0);
                q1 = fmaf(a1, a1, q1); q1 = fmaf(a3, a3, q1);
            }
            #pragma unroll
            for (int off = 4; off < 32; off <<= 1) {
                s0 += __shfl_xor_sync(0xffffffffu, s0, off);
                s1 += __shfl_xor_sync(0xffffffffu, s1, off);
                q0 += __shfl_xor_sync(0xffffffffu, q0, off);
                q1 += __shfl_xor_sync(0xffffffffu, q1, off);
            }
            if (lane < 4) {
                int c = bn * BNT + warp_n * 64 + nt * 8 + lane * 2;
                atomicAdd(&g_sum[c],   s0);  atomicAdd(&g_sum[c + 1],   s1);
                atomicAdd(&g_sumsq[c], q0);  atomicAdd(&g_sumsq[c + 1], q1);
            }
        }
        #pragma unroll
        for (int i2 = 0; i2 < 4; i2++)
            #pragma unroll
            for (int j2 = 0; j2 < 8; j2++)
                #pragma unroll
                for (int r2 = 0; r2 < 4; r2++) acc[i2][j2][r2] = 0.f;
    }
}

// ---------------- output: BN finalize (per-block) + xor-popcount -------------
__global__ __launch_bounds__(256)
void out_kernel(const float* __restrict__ gamma,
                const float* __restrict__ beta,
                float* __restrict__ out) {
    __shared__ float sAf[D_H];
    __shared__ float sBf[D_H];
    for (int j = threadIdx.x; j < D_H; j += 256) {
        float mu  = g_sum[j] * (1.f / B_ROWS);
        float var = g_sumsq[j] * (1.f / B_ROWS) - mu * mu;
        float inv = rsqrtf(var + BN_EPS);
        float A   = gamma[j] * inv;
        sAf[j] = A;
        sBf[j] = beta[j] - A * mu;
    }
    __syncthreads();

    int warp = (blockIdx.x * 256 + threadIdx.x) >> 5;
    int lane = threadIdx.x & 31;
    if (warp >= B_ROWS) return;

    const float* hrow = g_h + (size_t)warp * D_H;
    unsigned myword = 0;
    int adj[N_CLS];
    #pragma unroll
    for (int c = 0; c < N_CLS; c++) adj[c] = 0;

    for (int g = 0; g < 32; g++) {
        int col = g * 32 + lane;
        float v = fmaf(sAf[col], hrow[col], sBf[col]);
        unsigned w = __ballot_sync(0xffffffffu, v > 0.f);
        if (lane == g) myword = w;
        if (v == 0.f) {
            #pragma unroll
            for (int c = 0; c < N_CLS; c++)
                adj[c] += ((g_tbits[c][g] >> lane) & 1u) ? 1 : -1;
        }
    }
    #pragma unroll
    for (int c = 0; c < N_CLS; c++) {
        unsigned x = myword ^ g_tbits[c][lane];
        int s = 32 - 2 * __popc(x) + adj[c];
        s = __reduce_add_sync(0xffffffffu, s);
        if (lane == 0) out[(size_t)warp * N_CLS + c] = (float)s;
    }
}

// ---------------- launch ------------------------------------------------------
extern "C" void kernel_launch(void* const* d_in, const int* in_sizes, int n_in,
                              void* d_out, int out_size) {
    const float* x     = (const float*)d_in[0];
    const float* w1    = (const float*)d_in[1];
    const float* gamma = (const float*)d_in[2];
    const float* beta  = (const float*)d_in[3];
    const float* w2    = (const float*)d_in[4];
    float* out = (float*)d_out;

    cudaFuncSetAttribute(gemm1_kernel,
                         cudaFuncAttributeMaxDynamicSharedMemorySize, NSTAGE * STAGE_B);

    int sms = 148;
    cudaDeviceGetAttribute(&sms, cudaDevAttrMultiProcessorCount, 0);
    int grid = 2 * sms;
    if (grid > TILES) grid = TILES;

    prep_all_kernel<<<CONV_B + PREP_B + PAD_B, 256>>>(x, w1, w2);

    gemm1_kernel<<<grid, 128, NSTAGE * STAGE_B>>>();

    out_kernel<<<(B_ROWS * 32) / 256, 256>>>(gamma, beta, out);
}

// round 10
// speedup vs baseline: 1.0241x; 1.0241x over previous
#include <cuda_runtime.h>
#include <cuda_fp16.h>
#include <cstdint>

#define B_ROWS 65536
#define D_IN   784
#define D_H    1024
#define N_CLS  10
#define BN_EPS 1e-5f
#define KP     1600            // 2*784 fp16 planes + 32 zero pad = 25 * 64
#define KREAL  1568
#define BK     64
#define NIT    (KP / BK)       // 25
#define BMT    128
#define BNT    128
#define SROWB  144             // smem row stride bytes (128 data + 16 pad)
#define STAGE_B ((BMT + BNT) * SROWB)  // 36864 bytes
#define NSTAGE 3

// ---------------- device scratch ---------------------------------------------
__device__ __half g_xb[(size_t)B_ROWS * KP];   // x split into 2 fp16 planes
__device__ __half g_sb[(size_t)D_H * KP];      // sign(w1) tiled 2x, fp16
__device__ float    g_h[(size_t)B_ROWS * D_H];
__device__ float    g_sum[D_H];
__device__ float    g_sumsq[D_H];
__device__ unsigned g_tbits[N_CLS][32];

// ---------------- PTX helpers -------------------------------------------------
__device__ __forceinline__ uint32_t s2u(const void* p) {
    uint32_t a;
    asm("{ .reg .u64 t; cvta.to.shared.u64 t, %1; cvt.u32.u64 %0, t; }" : "=r"(a) : "l"(p));
    return a;
}
__device__ __forceinline__ void cpa16(uint32_t s, const void* g) {
    asm volatile("cp.async.cg.shared.global [%0], [%1], 16;" :: "r"(s), "l"(g) : "memory");
}
__device__ __forceinline__ void cp_commit() {
    asm volatile("cp.async.commit_group;" ::: "memory");
}
__device__ __forceinline__ void ldm4(uint32_t* a, uint32_t addr) {
    asm volatile("ldmatrix.sync.aligned.m8n8.x4.shared.b16 {%0,%1,%2,%3}, [%4];"
                 : "=r"(a[0]), "=r"(a[1]), "=r"(a[2]), "=r"(a[3]) : "r"(addr));
}
__device__ __forceinline__ void mma16816(float* c, const uint32_t* a, const uint32_t* b) {
    asm volatile("mma.sync.aligned.m16n8k16.row.col.f32.f16.f16.f32 "
                 "{%0,%1,%2,%3}, {%4,%5,%6,%7}, {%8,%9}, {%0,%1,%2,%3};"
                 : "+f"(c[0]), "+f"(c[1]), "+f"(c[2]), "+f"(c[3])
                 : "r"(a[0]), "r"(a[1]), "r"(a[2]), "r"(a[3]), "r"(b[0]), "r"(b[1]));
}

// ---------------- fused prep: convert x, binarize w1, pack w2, zero stats ----
#define CONV_B  ((B_ROWS * (D_IN / 4) + 255) / 256)    // 50176
#define PREP_B  ((D_H * KP + 255) / 256)               // 6400
#define PAD_B   ((B_ROWS * 4 + 255) / 256)             // 1024

__global__ void prep_all_kernel(const float* __restrict__ x,
                                const float* __restrict__ w1,
                                const float* __restrict__ w2) {
    int b = blockIdx.x;
    if (b < CONV_B) {
        size_t i = (size_t)b * 256 + threadIdx.x;
        if (i >= (size_t)B_ROWS * (D_IN / 4)) return;
        size_t m = i / (D_IN / 4);
        int k4 = (int)(i % (D_IN / 4)) * 4;
        float4 v = *(const float4*)(x + m * D_IN + k4);
        float f[4] = {v.x, v.y, v.z, v.w};
        __half2 hi2[2], lo2[2];
        #pragma unroll
        for (int j = 0; j < 2; j++) {
            __half h0 = __float2half_rn(f[2*j]);
            __half h1 = __float2half_rn(f[2*j+1]);
            float r0 = f[2*j]   - __half2float(h0);
            float r1 = f[2*j+1] - __half2float(h1);
            hi2[j] = __halves2half2(h0, h1);
            lo2[j] = __halves2half2(__float2half_rn(r0), __float2half_rn(r1));
        }
        __half2* row = (__half2*)(g_xb + m * KP);
        int p = k4 >> 1;
        row[p]          = hi2[0];  row[p + 1]          = hi2[1];
        row[p + D_IN/2] = lo2[0];  row[p + D_IN/2 + 1] = lo2[1];
    } else if (b < CONV_B + PREP_B) {
        int i = (b - CONV_B) * 256 + threadIdx.x;
        if (i < D_H * KP) {
            int n = i / KP, k = i % KP;
            float s = 0.f;
            if (k < KREAL) {
                float v = w1[n * D_IN + (k % D_IN)];
                s = (v > 0.f) ? 1.f : (v < 0.f ? -1.f : 0.f);
            }
            g_sb[i] = __float2half_rn(s);
        }
        if (i < D_H) { g_sum[i] = 0.f; g_sumsq[i] = 0.f; }
        if (i < N_CLS * 32) {
            int c = i >> 5, g = i & 31;
            unsigned w = 0;
            #pragma unroll
            for (int l = 0; l < 32; l++) {
                float v = w2[c * D_H + g * 32 + l];
                if (v > 0.f) w |= (1u << l);
            }
            g_tbits[c][g] = w;
        }
    } else {
        int i = (b - CONV_B - PREP_B) * 256 + threadIdx.x;
        if (i < B_ROWS * 4) {
            size_t row = (size_t)(i >> 2);
            *(uint4*)((char*)(g_xb + row * KP + KREAL) + (i & 3) * 16) =
                make_uint4(0, 0, 0, 0);
        }
    }
}

// ---------------- GEMM1 + fused BN stats -------------------------------------
// CTA tile 128x128, 4 warps (2x2), warp tile 64x64, BK=64, 3-stage cp.async,
// 2 CTAs/SM, register-stage fragment double-buffering. (R8 structure.)
__global__ __launch_bounds__(128, 2)
void gemm1_kernel() {
    extern __shared__ char smem[];
    const uint32_t sb = s2u(smem);
    const int tid = threadIdx.x, wid = tid >> 5, lane = tid & 31;
    const int bn = blockIdx.x, bm = blockIdx.y;
    const int warp_m = wid >> 1, warp_n = wid & 1;     // 2 x 2

    const __half* Ab = g_xb + (size_t)bm * BMT * KP;
    const __half* Bb = g_sb + (size_t)bn * BNT * KP;

    auto load_stage = [&](int it, int stage) {
        uint32_t sA = sb + stage * STAGE_B;
        uint32_t sBs = sA + BMT * SROWB;
        int k0 = it * BK;
        #pragma unroll
        for (int j = 0; j < 8; j++) {
            int idx = tid + j * 128;
            int row = idx >> 3, q = idx & 7;
            cpa16(sA + row * SROWB + q * 16,
                  (const char*)(Ab + (size_t)row * KP + k0) + q * 16);
        }
        #pragma unroll
        for (int j = 0; j < 8; j++) {
            int idx = tid + j * 128;
            int row = idx >> 3, q = idx & 7;
            cpa16(sBs + row * SROWB + q * 16,
                  (const char*)(Bb + (size_t)row * KP + k0) + q * 16);
        }
        cp_commit();
    };

    // precomputed ldmatrix intra-tile offsets
    const uint32_t a_off = (warp_m * 64 + (lane & 15)) * SROWB + (lane >> 4) * 16;
    const uint32_t b_off = (warp_n * 64 + (lane & 7) + ((lane >> 4) << 3)) * SROWB
                         + ((lane >> 3) & 1) * 16;

    float acc[4][8][4];
    #pragma unroll
    for (int i = 0; i < 4; i++)
        #pragma unroll
        for (int j = 0; j < 8; j++)
            #pragma unroll
            for (int r = 0; r < 4; r++) acc[i][j][r] = 0.f;

    load_stage(0, 0);
    load_stage(1, 1);

    uint32_t fa[2][4][4], fb[2][4][4];

    for (int i = 0; i < NIT; i++) {
        asm volatile("cp.async.wait_group 1;" ::: "memory");
        __syncthreads();
        uint32_t sA = sb + (i - i / 3 * 3) * STAGE_B;
        uint32_t sBs = sA + BMT * SROWB;

        // prefetch ks=0 fragments
        #pragma unroll
        for (int mt = 0; mt < 4; mt++)
            ldm4(fa[0][mt], sA + a_off + mt * 16 * SROWB);
        #pragma unroll
        for (int np = 0; np < 4; np++)
            ldm4(fb[0][np], sBs + b_off + np * 16 * SROWB);

        int nxt = i + 2;
        if (nxt < NIT) load_stage(nxt, nxt - nxt / 3 * 3);
        else cp_commit();

        #pragma unroll
        for (int ks = 0; ks < 4; ks++) {
            int cur = ks & 1;
            if (ks < 3) {
                int nb = cur ^ 1;
                uint32_t ko = (ks + 1) * 32;
                #pragma unroll
                for (int mt = 0; mt < 4; mt++)
                    ldm4(fa[nb][mt], sA + a_off + mt * 16 * SROWB + ko);
                #pragma unroll
                for (int np = 0; np < 4; np++)
                    ldm4(fb[nb][np], sBs + b_off + np * 16 * SROWB + ko);
            }
            #pragma unroll
            for (int mt = 0; mt < 4; mt++)
                #pragma unroll
                for (int nt = 0; nt < 8; nt++)
                    mma16816(acc[mt][nt], fa[cur][mt], fb[cur][nt >> 1] + (nt & 1) * 2);
        }
    }

    // ---------------- epilogue: write h + fused column stats ----------------
    float* Hb = g_h + (size_t)(bm * BMT) * D_H + bn * BNT;
    #pragma unroll
    for (int mt = 0; mt < 4; mt++) {
        int r0 = warp_m * 64 + mt * 16 + (lane >> 2);
        #pragma unroll
        for (int nt = 0; nt < 8; nt++) {
            int c = warp_n * 64 + nt * 8 + (lane & 3) * 2;
            *(float2*)(Hb + (size_t)r0 * D_H + c)       = make_float2(acc[mt][nt][0], acc[mt][nt][1]);
            *(float2*)(Hb + (size_t)(r0 + 8) * D_H + c) = make_float2(acc[mt][nt][2], acc[mt][nt][3]);
        }
    }
    #pragma unroll
    for (int nt = 0; nt < 8; nt++) {
        float s0 = 0.f, s1 = 0.f, q0 = 0.f, q1 = 0.f;
        #pragma unroll
        for (int mt = 0; mt < 4; mt++) {
            float a0 = acc[mt][nt][0], a1 = acc[mt][nt][1];
            float a2 = acc[mt][nt][2], a3 = acc[mt][nt][3];
            s0 += a0 + a2; s1 += a1 + a3;
            q0 = fmaf(a0, a0, q0); q0 = fmaf(a2, a2, q0);
            q1 = fmaf(a1, a1, q1); q1 = fmaf(a3, a3, q1);
        }
        #pragma unroll
        for (int off = 4; off < 32; off <<= 1) {
            s0 += __shfl_xor_sync(0xffffffffu, s0, off);
            s1 += __shfl_xor_sync(0xffffffffu, s1, off);
            q0 += __shfl_xor_sync(0xffffffffu, q0, off);
            q1 += __shfl_xor_sync(0xffffffffu, q1, off);
        }
        if (lane < 4) {
            int c = bn * BNT + warp_n * 64 + nt * 8 + lane * 2;
            atomicAdd(&g_sum[c],   s0);  atomicAdd(&g_sum[c + 1],   s1);
            atomicAdd(&g_sumsq[c], q0);  atomicAdd(&g_sumsq[c + 1], q1);
        }
    }
}

// ---------------- output: BN finalize (per-block) + xor-popcount -------------
__global__ __launch_bounds__(256)
void out_kernel(const float* __restrict__ gamma,
                const float* __restrict__ beta,
                float* __restrict__ out) {
    __shared__ float sAf[D_H];
    __shared__ float sBf[D_H];
    for (int j = threadIdx.x; j < D_H; j += 256) {
        float mu  = g_sum[j] * (1.f / B_ROWS);
        float var = g_sumsq[j] * (1.f / B_ROWS) - mu * mu;
        float inv = rsqrtf(var + BN_EPS);
        float A   = gamma[j] * inv;
        sAf[j] = A;
        sBf[j] = beta[j] - A * mu;
    }
    __syncthreads();

    int warp = (blockIdx.x * 256 + threadIdx.x) >> 5;
    int lane = threadIdx.x & 31;
    if (warp >= B_ROWS) return;

    const float* hrow = g_h + (size_t)warp * D_H;
    unsigned myword = 0;
    int adj[N_CLS];
    #pragma unroll
    for (int c = 0; c < N_CLS; c++) adj[c] = 0;

    for (int g = 0; g < 32; g++) {
        int col = g * 32 + lane;
        float v = fmaf(sAf[col], hrow[col], sBf[col]);
        unsigned w = __ballot_sync(0xffffffffu, v > 0.f);
        if (lane == g) myword = w;
        if (v == 0.f) {
            #pragma unroll
            for (int c = 0; c < N_CLS; c++)
                adj[c] += ((g_tbits[c][g] >> lane) & 1u) ? 1 : -1;
        }
    }
    #pragma unroll
    for (int c = 0; c < N_CLS; c++) {
        unsigned x = myword ^ g_tbits[c][lane];
        int s = 32 - 2 * __popc(x) + adj[c];
        s = __reduce_add_sync(0xffffffffu, s);
        if (lane == 0) out[(size_t)warp * N_CLS + c] = (float)s;
    }
}

// ---------------- launch ------------------------------------------------------
extern "C" void kernel_launch(void* const* d_in, const int* in_sizes, int n_in,
                              void* d_out, int out_size) {
    const float* x     = (const float*)d_in[0];
    const float* w1    = (const float*)d_in[1];
    const float* gamma = (const float*)d_in[2];
    const float* beta  = (const float*)d_in[3];
    const float* w2    = (const float*)d_in[4];
    float* out = (float*)d_out;

    cudaFuncSetAttribute(gemm1_kernel,
                         cudaFuncAttributeMaxDynamicSharedMemorySize, NSTAGE * STAGE_B);

    prep_all_kernel<<<CONV_B + PREP_B + PAD_B, 256>>>(x, w1, w2);

    gemm1_kernel<<<dim3(D_H / BNT, B_ROWS / BMT), 128, NSTAGE * STAGE_B>>>();

    out_kernel<<<(B_ROWS * 32) / 256, 256>>>(gamma, beta, out);
}

// round 11
// speedup vs baseline: 1.1800x; 1.1522x over previous
#include <cuda_runtime.h>
#include <cuda_fp16.h>
#include <cstdint>

#define B_ROWS 65536
#define D_IN   784
#define D_H    1024
#define N_CLS  10
#define BN_EPS 1e-5f
#define KP     1600            // 2*784 fp16 planes + 32 zero pad = 25 * 64
#define KREAL  1568
#define BK     64
#define NIT    (KP / BK)       // 25
#define BMT    128
#define BNT    128
#define SROWB  144             // smem row stride bytes (128 data + 16 pad)
#define STAGE_B ((BMT + BNT) * SROWB)  // 36864 bytes
#define NSTAGE 3

// ---------------- device scratch ---------------------------------------------
__device__ __half g_xb[(size_t)B_ROWS * KP];   // x split into 2 fp16 planes
__device__ __half g_sb[(size_t)D_H * KP];      // sign(w1) tiled 2x, fp16
__device__ float    g_h[(size_t)B_ROWS * D_H];
__device__ float    g_sum[D_H];
__device__ float    g_sumsq[D_H];
__device__ unsigned g_tbits[N_CLS][32];

// ---------------- PTX helpers -------------------------------------------------
__device__ __forceinline__ uint32_t s2u(const void* p) {
    uint32_t a;
    asm("{ .reg .u64 t; cvta.to.shared.u64 t, %1; cvt.u32.u64 %0, t; }" : "=r"(a) : "l"(p));
    return a;
}
__device__ __forceinline__ void cpa16(uint32_t s, const void* g) {
    asm volatile("cp.async.cg.shared.global [%0], [%1], 16;" :: "r"(s), "l"(g) : "memory");
}
__device__ __forceinline__ void cp_commit() {
    asm volatile("cp.async.commit_group;" ::: "memory");
}
__device__ __forceinline__ void ldm4(uint32_t* a, uint32_t addr) {
    asm volatile("ldmatrix.sync.aligned.m8n8.x4.shared.b16 {%0,%1,%2,%3}, [%4];"
                 : "=r"(a[0]), "=r"(a[1]), "=r"(a[2]), "=r"(a[3]) : "r"(addr));
}
__device__ __forceinline__ void mma16816(float* c, const uint32_t* a, const uint32_t* b) {
    asm volatile("mma.sync.aligned.m16n8k16.row.col.f32.f16.f16.f32 "
                 "{%0,%1,%2,%3}, {%4,%5,%6,%7}, {%8,%9}, {%0,%1,%2,%3};"
                 : "+f"(c[0]), "+f"(c[1]), "+f"(c[2]), "+f"(c[3])
                 : "r"(a[0]), "r"(a[1]), "r"(a[2]), "r"(a[3]), "r"(b[0]), "r"(b[1]));
}

// ---------------- fused prep: convert x, binarize w1, pack w2, zero stats ----
#define CONV_B  ((B_ROWS * (D_IN / 4) + 255) / 256)    // 50176
#define PREP_B  ((D_H * KP + 255) / 256)               // 6400
#define PAD_B   ((B_ROWS * 4 + 255) / 256)             // 1024

__global__ void prep_all_kernel(const float* __restrict__ x,
                                const float* __restrict__ w1,
                                const float* __restrict__ w2) {
    int b = blockIdx.x;
    if (b < CONV_B) {
        size_t i = (size_t)b * 256 + threadIdx.x;
        if (i >= (size_t)B_ROWS * (D_IN / 4)) return;
        size_t m = i / (D_IN / 4);
        int k4 = (int)(i % (D_IN / 4)) * 4;
        float4 v = *(const float4*)(x + m * D_IN + k4);
        float f[4] = {v.x, v.y, v.z, v.w};
        __half2 hi2[2], lo2[2];
        #pragma unroll
        for (int j = 0; j < 2; j++) {
            __half h0 = __float2half_rn(f[2*j]);
            __half h1 = __float2half_rn(f[2*j+1]);
            float r0 = f[2*j]   - __half2float(h0);
            float r1 = f[2*j+1] - __half2float(h1);
            hi2[j] = __halves2half2(h0, h1);
            lo2[j] = __halves2half2(__float2half_rn(r0), __float2half_rn(r1));
        }
        __half2* row = (__half2*)(g_xb + m * KP);
        int p = k4 >> 1;
        row[p]          = hi2[0];  row[p + 1]          = hi2[1];
        row[p + D_IN/2] = lo2[0];  row[p + D_IN/2 + 1] = lo2[1];
    } else if (b < CONV_B + PREP_B) {
        int i = (b - CONV_B) * 256 + threadIdx.x;
        if (i < D_H * KP) {
            int n = i / KP, k = i % KP;
            float s = 0.f;
            if (k < KREAL) {
                float v = w1[n * D_IN + (k % D_IN)];
                s = (v > 0.f) ? 1.f : (v < 0.f ? -1.f : 0.f);
            }
            g_sb[i] = __float2half_rn(s);
        }
        if (i < D_H) { g_sum[i] = 0.f; g_sumsq[i] = 0.f; }
        if (i < N_CLS * 32) {
            int c = i >> 5, g = i & 31;
            unsigned w = 0;
            #pragma unroll
            for (int l = 0; l < 32; l++) {
                float v = w2[c * D_H + g * 32 + l];
                if (v > 0.f) w |= (1u << l);
            }
            g_tbits[c][g] = w;
        }
    } else {
        int i = (b - CONV_B - PREP_B) * 256 + threadIdx.x;
        if (i < B_ROWS * 4) {
            size_t row = (size_t)(i >> 2);
            *(uint4*)((char*)(g_xb + row * KP + KREAL) + (i & 3) * 16) =
                make_uint4(0, 0, 0, 0);
        }
    }
}

// ---------------- GEMM1 + fused BN stats -------------------------------------
// CTA tile 128x128, 4 warps (2x2), warp tile 64x64, BK=64, 3-stage cp.async,
// 2 CTAs/SM, register-stage fragment double-buffering. (R8 structure.)
__global__ __launch_bounds__(128, 2)
void gemm1_kernel() {
    extern __shared__ char smem[];
    const uint32_t sb = s2u(smem);
    const int tid = threadIdx.x, wid = tid >> 5, lane = tid & 31;
    const int bn = blockIdx.x, bm = blockIdx.y;
    const int warp_m = wid >> 1, warp_n = wid & 1;     // 2 x 2

    const __half* Ab = g_xb + (size_t)bm * BMT * KP;
    const __half* Bb = g_sb + (size_t)bn * BNT * KP;

    auto load_stage = [&](int it, int stage) {
        uint32_t sA = sb + stage * STAGE_B;
        uint32_t sBs = sA + BMT * SROWB;
        int k0 = it * BK;
        #pragma unroll
        for (int j = 0; j < 8; j++) {
            int idx = tid + j * 128;
            int row = idx >> 3, q = idx & 7;
            cpa16(sA + row * SROWB + q * 16,
                  (const char*)(Ab + (size_t)row * KP + k0) + q * 16);
        }
        #pragma unroll
        for (int j = 0; j < 8; j++) {
            int idx = tid + j * 128;
            int row = idx >> 3, q = idx & 7;
            cpa16(sBs + row * SROWB + q * 16,
                  (const char*)(Bb + (size_t)row * KP + k0) + q * 16);
        }
        cp_commit();
    };

    // precomputed ldmatrix intra-tile offsets
    const uint32_t a_off = (warp_m * 64 + (lane & 15)) * SROWB + (lane >> 4) * 16;
    const uint32_t b_off = (warp_n * 64 + (lane & 7) + ((lane >> 4) << 3)) * SROWB
                         + ((lane >> 3) & 1) * 16;

    float acc[4][8][4];
    #pragma unroll
    for (int i = 0; i < 4; i++)
        #pragma unroll
        for (int j = 0; j < 8; j++)
            #pragma unroll
            for (int r = 0; r < 4; r++) acc[i][j][r] = 0.f;

    load_stage(0, 0);
    load_stage(1, 1);

    uint32_t fa[2][4][4], fb[2][4][4];

    for (int i = 0; i < NIT; i++) {
        asm volatile("cp.async.wait_group 1;" ::: "memory");
        __syncthreads();
        uint32_t sA = sb + (i - i / 3 * 3) * STAGE_B;
        uint32_t sBs = sA + BMT * SROWB;

        // prefetch ks=0 fragments
        #pragma unroll
        for (int mt = 0; mt < 4; mt++)
            ldm4(fa[0][mt], sA + a_off + mt * 16 * SROWB);
        #pragma unroll
        for (int np = 0; np < 4; np++)
            ldm4(fb[0][np], sBs + b_off + np * 16 * SROWB);

        int nxt = i + 2;
        if (nxt < NIT) load_stage(nxt, nxt - nxt / 3 * 3);
        else cp_commit();

        #pragma unroll
        for (int ks = 0; ks < 4; ks++) {
            int cur = ks & 1;
            if (ks < 3) {
                int nb = cur ^ 1;
                uint32_t ko = (ks + 1) * 32;
                #pragma unroll
                for (int mt = 0; mt < 4; mt++)
                    ldm4(fa[nb][mt], sA + a_off + mt * 16 * SROWB + ko);
                #pragma unroll
                for (int np = 0; np < 4; np++)
                    ldm4(fb[nb][np], sBs + b_off + np * 16 * SROWB + ko);
            }
            #pragma unroll
            for (int mt = 0; mt < 4; mt++)
                #pragma unroll
                for (int nt = 0; nt < 8; nt++)
                    mma16816(acc[mt][nt], fa[cur][mt], fb[cur][nt >> 1] + (nt & 1) * 2);
        }
    }

    // ---------------- epilogue: write h + fused column stats ----------------
    float* Hb = g_h + (size_t)(bm * BMT) * D_H + bn * BNT;
    #pragma unroll
    for (int mt = 0; mt < 4; mt++) {
        int r0 = warp_m * 64 + mt * 16 + (lane >> 2);
        #pragma unroll
        for (int nt = 0; nt < 8; nt++) {
            int c = warp_n * 64 + nt * 8 + (lane & 3) * 2;
            *(float2*)(Hb + (size_t)r0 * D_H + c)       = make_float2(acc[mt][nt][0], acc[mt][nt][1]);
            *(float2*)(Hb + (size_t)(r0 + 8) * D_H + c) = make_float2(acc[mt][nt][2], acc[mt][nt][3]);
        }
    }
    #pragma unroll
    for (int nt = 0; nt < 8; nt++) {
        float s0 = 0.f, s1 = 0.f, q0 = 0.f, q1 = 0.f;
        #pragma unroll
        for (int mt = 0; mt < 4; mt++) {
            float a0 = acc[mt][nt][0], a1 = acc[mt][nt][1];
            float a2 = acc[mt][nt][2], a3 = acc[mt][nt][3];
            s0 += a0 + a2; s1 += a1 + a3;
            q0 = fmaf(a0, a0, q0); q0 = fmaf(a2, a2, q0);
            q1 = fmaf(a1, a1, q1); q1 = fmaf(a3, a3, q1);
        }
        #pragma unroll
        for (int off = 4; off < 32; off <<= 1) {
            s0 += __shfl_xor_sync(0xffffffffu, s0, off);
            s1 += __shfl_xor_sync(0xffffffffu, s1, off);
            q0 += __shfl_xor_sync(0xffffffffu, q0, off);
            q1 += __shfl_xor_sync(0xffffffffu, q1, off);
        }
        if (lane < 4) {
            int c = bn * BNT + warp_n * 64 + nt * 8 + lane * 2;
            atomicAdd(&g_sum[c],   s0);  atomicAdd(&g_sum[c + 1],   s1);
            atomicAdd(&g_sumsq[c], q0);  atomicAdd(&g_sumsq[c + 1], q1);
        }
    }
}

// ---------------- output: BN finalize + xor-popcount (high-MLP version) ------
__global__ __launch_bounds__(256)
void out_kernel(const float* __restrict__ gamma,
                const float* __restrict__ beta,
                float* __restrict__ out) {
    __shared__ float sAf[D_H];
    __shared__ float sBf[D_H];
    for (int j = threadIdx.x; j < D_H; j += 256) {
        float mu  = g_sum[j] * (1.f / B_ROWS);
        float var = g_sumsq[j] * (1.f / B_ROWS) - mu * mu;
        float inv = rsqrtf(var + BN_EPS);
        float A   = gamma[j] * inv;
        sAf[j] = A;
        sBf[j] = beta[j] - A * mu;
    }
    __syncthreads();

    int warp = (blockIdx.x * 256 + threadIdx.x) >> 5;
    int lane = threadIdx.x & 31;
    if (warp >= B_ROWS) return;

    const float* hrow = g_h + (size_t)warp * D_H;

    // phase 1: batch all loads + fmaf (independent -> MLP 32)
    float v[32];
    #pragma unroll
    for (int g = 0; g < 32; g++) {
        int col = g * 32 + lane;
        v[g] = fmaf(sAf[col], hrow[col], sBf[col]);
    }

    // phase 2: ballots on register operands
    unsigned myword = 0;
    bool anyzero = false;
    #pragma unroll
    for (int g = 0; g < 32; g++) {
        unsigned w = __ballot_sync(0xffffffffu, v[g] > 0.f);
        if (lane == g) myword = w;
        anyzero |= (v[g] == 0.f);
    }

    // phase 3: rare exact-zero adjustment (sign(0)=0), hoisted off hot path
    int adj[N_CLS];
    #pragma unroll
    for (int c = 0; c < N_CLS; c++) adj[c] = 0;
    if (__any_sync(0xffffffffu, anyzero)) {
        #pragma unroll
        for (int g = 0; g < 32; g++) {
            if (v[g] == 0.f) {
                #pragma unroll
                for (int c = 0; c < N_CLS; c++)
                    adj[c] += ((g_tbits[c][g] >> lane) & 1u) ? 1 : -1;
            }
        }
    }

    #pragma unroll
    for (int c = 0; c < N_CLS; c++) {
        unsigned x = myword ^ g_tbits[c][lane];
        int s = 32 - 2 * __popc(x) + adj[c];
        s = __reduce_add_sync(0xffffffffu, s);
        if (lane == 0) out[(size_t)warp * N_CLS + c] = (float)s;
    }
}

// ---------------- launch ------------------------------------------------------
extern "C" void kernel_launch(void* const* d_in, const int* in_sizes, int n_in,
                              void* d_out, int out_size) {
    const float* x     = (const float*)d_in[0];
    const float* w1    = (const float*)d_in[1];
    const float* gamma = (const float*)d_in[2];
    const float* beta  = (const float*)d_in[3];
    const float* w2    = (const float*)d_in[4];
    float* out = (float*)d_out;

    cudaFuncSetAttribute(gemm1_kernel,
                         cudaFuncAttributeMaxDynamicSharedMemorySize, NSTAGE * STAGE_B);

    prep_all_kernel<<<CONV_B + PREP_B + PAD_B, 256>>>(x, w1, w2);

    gemm1_kernel<<<dim3(D_H / BNT, B_ROWS / BMT), 128, NSTAGE * STAGE_B>>>();

    out_kernel<<<(B_ROWS * 32) / 256, 256>>>(gamma, beta, out);
}

// round 13
// speedup vs baseline: 1.2325x; 1.0444x over previous
#include <cuda_runtime.h>
#include <cuda_fp16.h>
#include <cstdint>

#define B_ROWS 65536
#define D_IN   784
#define D_H    1024
#define N_CLS  10
#define BN_EPS 1e-5f
#define KP     1600            // 2*784 fp16 planes + 32 zero pad = 25 * 64
#define KREAL  1568
#define BK     64
#define NIT    (KP / BK)       // 25
#define NKT    (KP / 16)       // 100 k16-tiles
#define BMT    128
#define BNT    128
#define SROWB  144             // A smem row stride bytes (128 data + 16 pad)
#define STAGE_B (BMT * SROWB)  // 18432 bytes (A only)
#define NSTAGE 3

// ---------------- device scratch ---------------------------------------------
__device__ __half    g_xb[(size_t)B_ROWS * KP];   // x split into 2 fp16 planes
// B sign bytes in mma-fragment order: [strip s(16)][kt(100)][half(2)][lane(32)][4 words]
#define BSP_WORDS (16 * NKT * 2 * 32 * 4)         // 409600 words = 1.6 MB
__device__ unsigned  g_bsp[BSP_WORDS];
__device__ float     g_h[(size_t)B_ROWS * D_H];
__device__ float     g_sum[D_H];
__device__ float     g_sumsq[D_H];
__device__ unsigned  g_tbits[N_CLS][32];

// ---------------- PTX helpers -------------------------------------------------
__device__ __forceinline__ uint32_t s2u(const void* p) {
    uint32_t a;
    asm("{ .reg .u64 t; cvta.to.shared.u64 t, %1; cvt.u32.u64 %0, t; }" : "=r"(a) : "l"(p));
    return a;
}
__device__ __forceinline__ void cpa16(uint32_t s, const void* g) {
    asm volatile("cp.async.cg.shared.global [%0], [%1], 16;" :: "r"(s), "l"(g) : "memory");
}
__device__ __forceinline__ void cp_commit() {
    asm volatile("cp.async.commit_group;" ::: "memory");
}
__device__ __forceinline__ void ldm4(uint32_t* a, uint32_t addr) {
    asm volatile("ldmatrix.sync.aligned.m8n8.x4.shared.b16 {%0,%1,%2,%3}, [%4];"
                 : "=r"(a[0]), "=r"(a[1]), "=r"(a[2]), "=r"(a[3]) : "r"(addr));
}
__device__ __forceinline__ void mma16816(float* c, const uint32_t* a, const uint32_t* b) {
    asm volatile("mma.sync.aligned.m16n8k16.row.col.f32.f16.f16.f32 "
                 "{%0,%1,%2,%3}, {%4,%5,%6,%7}, {%8,%9}, {%0,%1,%2,%3};"
                 : "+f"(c[0]), "+f"(c[1]), "+f"(c[2]), "+f"(c[3])
                 : "r"(a[0]), "r"(a[1]), "r"(a[2]), "r"(a[3]), "r"(b[0]), "r"(b[1]));
}
// expand 4 sign bytes (word W) into two fp16x2 ±1 registers
#define EXPAND_B(W, r0, r1) do {                                   \
    (r0) = 0x3C003C00u ^ __byte_perm((W), 0u, 0x1404);             \
    (r1) = 0x3C003C00u ^ __byte_perm((W), 0u, 0x3424);             \
} while (0)

// ---------------- fused prep --------------------------------------------------
#define CONV_B  ((B_ROWS * (D_IN / 4) + 255) / 256)    // 50176
#define BSP_B   ((BSP_WORDS + 255) / 256)              // 1600
#define PAD_B   ((B_ROWS * 4 + 255) / 256)             // 1024
#define MISC_B  4                                      // covers D_H=1024 stat zeroing

__global__ void prep_all_kernel(const float* __restrict__ x,
                                const float* __restrict__ w1,
                                const float* __restrict__ w2) {
    int b = blockIdx.x;
    if (b < CONV_B) {
        size_t i = (size_t)b * 256 + threadIdx.x;
        if (i >= (size_t)B_ROWS * (D_IN / 4)) return;
        size_t m = i / (D_IN / 4);
        int k4 = (int)(i % (D_IN / 4)) * 4;
        float4 v = *(const float4*)(x + m * D_IN + k4);
        float f[4] = {v.x, v.y, v.z, v.w};
        __half2 hi2[2], lo2[2];
        #pragma unroll
        for (int j = 0; j < 2; j++) {
            __half h0 = __float2half_rn(f[2*j]);
            __half h1 = __float2half_rn(f[2*j+1]);
            float r0 = f[2*j]   - __half2float(h0);
            float r1 = f[2*j+1] - __half2float(h1);
            hi2[j] = __halves2half2(h0, h1);
            lo2[j] = __halves2half2(__float2half_rn(r0), __float2half_rn(r1));
        }
        __half2* row = (__half2*)(g_xb + m * KP);
        int p = k4 >> 1;
        row[p]          = hi2[0];  row[p + 1]          = hi2[1];
        row[p + D_IN/2] = lo2[0];  row[p + D_IN/2 + 1] = lo2[1];
    } else if (b < CONV_B + BSP_B) {
        int widx = (b - CONV_B) * 256 + threadIdx.x;
        if (widx < BSP_WORDS) {
            int wi   = widx & 3;
            int lane = (widx >> 2) & 31;
            int half = (widx >> 7) & 1;
            int skt  = widx >> 8;            // s*100 + kt
            int kt   = skt % NKT;
            int s    = skt / NKT;
            int ntile = half * 4 + wi;
            int n  = (s * 8 + ntile) * 8 + (lane >> 2);
            int kb = kt * 16 + (lane & 3) * 2;
            int kk[4] = {kb, kb + 1, kb + 8, kb + 9};
            unsigned wbits = 0;
            #pragma unroll
            for (int j = 0; j < 4; j++) {
                int k = kk[j];
                unsigned sgn = 0;
                if (k < KREAL) {
                    float v = w1[n * D_IN + (k >= D_IN ? k - D_IN : k)];
                    sgn = (v < 0.f) ? 0x80u : 0u;
                }
                wbits |= sgn << (8 * j);
            }
            g_bsp[widx] = wbits;
        }
    } else if (b < CONV_B + BSP_B + PAD_B) {
        int i = (b - CONV_B - BSP_B) * 256 + threadIdx.x;
        if (i < B_ROWS * 4) {
            size_t row = (size_t)(i >> 2);
            *(uint4*)((char*)(g_xb + row * KP + KREAL) + (i & 3) * 16) =
                make_uint4(0, 0, 0, 0);
        }
    } else {
        int i = (b - CONV_B - BSP_B - PAD_B) * 256 + threadIdx.x;
        if (i < D_H) { g_sum[i] = 0.f; g_sumsq[i] = 0.f; }
        if (i < N_CLS * 32) {
            int c = i >> 5, g = i & 31;
            unsigned w = 0;
            #pragma unroll
            for (int l = 0; l < 32; l++) {
                float v = w2[c * D_H + g * 32 + l];
                if (v > 0.f) w |= (1u << l);
            }
            g_tbits[c][g] = w;
        }
    }
}

// ---------------- GEMM1 + fused BN stats -------------------------------------
// CTA tile 128x128, 4 warps (2x2), warp tile 64x64, BK=64, 3-stage cp.async
// for A only; B synthesized from L1-resident sign bytes (byte_perm + xor).
__global__ __launch_bounds__(128, 2)
void gemm1_kernel() {
    extern __shared__ char smem[];
    const uint32_t sb = s2u(smem);
    const int tid = threadIdx.x, wid = tid >> 5, lane = tid & 31;
    const int bn = blockIdx.x, bm = blockIdx.y;
    const int warp_m = wid >> 1, warp_n = wid & 1;     // 2 x 2

    const __half* Ab = g_xb + (size_t)bm * BMT * KP;
    // B sign base for this (bn, warp_n) strip; uint4 granularity
    const uint4* Bp = reinterpret_cast<const uint4*>(g_bsp)
                    + (size_t)(bn * 2 + warp_n) * NKT * 64 + lane;

    auto load_stage = [&](int it, int stage) {
        uint32_t sA = sb + stage * STAGE_B;
        int k0 = it * BK;
        #pragma unroll
        for (int j = 0; j < 8; j++) {
            int idx = tid + j * 128;
            int row = idx >> 3, q = idx & 7;
            cpa16(sA + row * SROWB + q * 16,
                  (const char*)(Ab + (size_t)row * KP + k0) + q * 16);
        }
        cp_commit();
    };

    const uint32_t a_off = (warp_m * 64 + (lane & 15)) * SROWB + (lane >> 4) * 16;

    float acc[4][8][4];
    #pragma unroll
    for (int i = 0; i < 4; i++)
        #pragma unroll
        for (int j = 0; j < 8; j++)
            #pragma unroll
            for (int r = 0; r < 4; r++) acc[i][j][r] = 0.f;

    load_stage(0, 0);
    load_stage(1, 1);

    uint32_t fa[2][4][4];
    uint4 wb[2][2];

    for (int i = 0; i < NIT; i++) {
        asm volatile("cp.async.wait_group 1;" ::: "memory");
        __syncthreads();
        uint32_t sA = sb + (i - i / 3 * 3) * STAGE_B;
        const int kt0 = i * 4;

        // prefetch ks=0: A fragments from smem, B sign words from global
        #pragma unroll
        for (int mt = 0; mt < 4; mt++)
            ldm4(fa[0][mt], sA + a_off + mt * 16 * SROWB);
        wb[0][0] = Bp[kt0 * 64];
        wb[0][1] = Bp[kt0 * 64 + 32];

        int nxt = i + 2;
        if (nxt < NIT) load_stage(nxt, nxt - nxt / 3 * 3);
        else cp_commit();

        #pragma unroll
        for (int ks = 0; ks < 4; ks++) {
            const int cur = ks & 1;
            if (ks < 3) {
                const int nb = cur ^ 1;
                uint32_t ko = (ks + 1) * 32;
                #pragma unroll
                for (int mt = 0; mt < 4; mt++)
                    ldm4(fa[nb][mt], sA + a_off + mt * 16 * SROWB + ko);
                wb[nb][0] = Bp[(kt0 + ks + 1) * 64];
                wb[nb][1] = Bp[(kt0 + ks + 1) * 64 + 32];
            }
            // expand 8 sign words -> 16 fp16x2 (+/-1) B registers
            uint32_t br[16];
            EXPAND_B(wb[cur][0].x, br[0],  br[1]);
            EXPAND_B(wb[cur][0].y, br[2],  br[3]);
            EXPAND_B(wb[cur][0].z, br[4],  br[5]);
            EXPAND_B(wb[cur][0].w, br[6],  br[7]);
            EXPAND_B(wb[cur][1].x, br[8],  br[9]);
            EXPAND_B(wb[cur][1].y, br[10], br[11]);
            EXPAND_B(wb[cur][1].z, br[12], br[13]);
            EXPAND_B(wb[cur][1].w, br[14], br[15]);
            #pragma unroll
            for (int mt = 0; mt < 4; mt++)
                #pragma unroll
                for (int nt = 0; nt < 8; nt++)
                    mma16816(acc[mt][nt], fa[cur][mt], br + nt * 2);
        }
    }

    // ---------------- epilogue: write h + fused column stats ----------------
    float* Hb = g_h + (size_t)(bm * BMT) * D_H + bn * BNT;
    #pragma unroll
    for (int mt = 0; mt < 4; mt++) {
        int r0 = warp_m * 64 + mt * 16 + (lane >> 2);
        #pragma unroll
        for (int nt = 0; nt < 8; nt++) {
            int c = warp_n * 64 + nt * 8 + (lane & 3) * 2;
            *(float2*)(Hb + (size_t)r0 * D_H + c)       = make_float2(acc[mt][nt][0], acc[mt][nt][1]);
            *(float2*)(Hb + (size_t)(r0 + 8) * D_H + c) = make_float2(acc[mt][nt][2], acc[mt][nt][3]);
        }
    }
    #pragma unroll
    for (int nt = 0; nt < 8; nt++) {
        float s0 = 0.f, s1 = 0.f, q0 = 0.f, q1 = 0.f;
        #pragma unroll
        for (int mt = 0; mt < 4; mt++) {
            float a0 = acc[mt][nt][0], a1 = acc[mt][nt][1];
            float a2 = acc[mt][nt][2], a3 = acc[mt][nt][3];
            s0 += a0 + a2; s1 += a1 + a3;
            q0 = fmaf(a0, a0, q0); q0 = fmaf(a2, a2, q0);
            q1 = fmaf(a1, a1, q1); q1 = fmaf(a3, a3, q1);
        }
        #pragma unroll
        for (int off = 4; off < 32; off <<= 1) {
            s0 += __shfl_xor_sync(0xffffffffu, s0, off);
            s1 += __shfl_xor_sync(0xffffffffu, s1, off);
            q0 += __shfl_xor_sync(0xffffffffu, q0, off);
            q1 += __shfl_xor_sync(0xffffffffu, q1, off);
        }
        if (lane < 4) {
            int c = bn * BNT + warp_n * 64 + nt * 8 + lane * 2;
            atomicAdd(&g_sum[c],   s0);  atomicAdd(&g_sum[c + 1],   s1);
            atomicAdd(&g_sumsq[c], q0);  atomicAdd(&g_sumsq[c + 1], q1);
        }
    }
}

// ---------------- output: BN finalize + xor-popcount (high-MLP version) ------
__global__ __launch_bounds__(256)
void out_kernel(const float* __restrict__ gamma,
                const float* __restrict__ beta,
                float* __restrict__ out) {
    __shared__ float sAf[D_H];
    __shared__ float sBf[D_H];
    for (int j = threadIdx.x; j < D_H; j += 256) {
        float mu  = g_sum[j] * (1.f / B_ROWS);
        float var = g_sumsq[j] * (1.f / B_ROWS) - mu * mu;
        float inv = rsqrtf(var + BN_EPS);
        float A   = gamma[j] * inv;
        sAf[j] = A;
        sBf[j] = beta[j] - A * mu;
    }
    __syncthreads();

    int warp = (blockIdx.x * 256 + threadIdx.x) >> 5;
    int lane = threadIdx.x & 31;
    if (warp >= B_ROWS) return;

    const float* hrow = g_h + (size_t)warp * D_H;

    float v[32];
    #pragma unroll
    for (int g = 0; g < 32; g++) {
        int col = g * 32 + lane;
        v[g] = fmaf(sAf[col], hrow[col], sBf[col]);
    }

    unsigned myword = 0;
    bool anyzero = false;
    #pragma unroll
    for (int g = 0; g < 32; g++) {
        unsigned w = __ballot_sync(0xffffffffu, v[g] > 0.f);
        if (lane == g) myword = w;
        anyzero |= (v[g] == 0.f);
    }

    int adj[N_CLS];
    #pragma unroll
    for (int c = 0; c < N_CLS; c++) adj[c] = 0;
    if (__any_sync(0xffffffffu, anyzero)) {
        #pragma unroll
        for (int g = 0; g < 32; g++) {
            if (v[g] == 0.f) {
                #pragma unroll
                for (int c = 0; c < N_CLS; c++)
                    adj[c] += ((g_tbits[c][g] >> lane) & 1u) ? 1 : -1;
            }
        }
    }

    #pragma unroll
    for (int c = 0; c < N_CLS; c++) {
        unsigned x = myword ^ g_tbits[c][lane];
        int s = 32 - 2 * __popc(x) + adj[c];
        s = __reduce_add_sync(0xffffffffu, s);
        if (lane == 0) out[(size_t)warp * N_CLS + c] = (float)s;
    }
}

// ---------------- launch ------------------------------------------------------
extern "C" void kernel_launch(void* const* d_in, const int* in_sizes, int n_in,
                              void* d_out, int out_size) {
    const float* x     = (const float*)d_in[0];
    const float* w1    = (const float*)d_in[1];
    const float* gamma = (const float*)d_in[2];
    const float* beta  = (const float*)d_in[3];
    const float* w2    = (const float*)d_in[4];
    float* out = (float*)d_out;

    cudaFuncSetAttribute(gemm1_kernel,
                         cudaFuncAttributeMaxDynamicSharedMemorySize, NSTAGE * STAGE_B);

    prep_all_kernel<<<CONV_B + BSP_B + PAD_B + MISC_B, 256>>>(x, w1, w2);

    gemm1_kernel<<<dim3(D_H / BNT, B_ROWS / BMT), 128, NSTAGE * STAGE_B>>>();

    out_kernel<<<(B_ROWS * 32) / 256, 256>>>(gamma, beta, out);
}